// round 1
// baseline (speedup 1.0000x reference)
#include <cuda_runtime.h>
#include <cstdint>

// Problem constants
#define N_ROWS 8192
#define D_COLS 1024
#define D4     (D_COLS / 4)          // 256 float4 columns
#define NBLK1  256                   // kernel1 blocks
#define ROWS_PER_BLK (N_ROWS / NBLK1) // 32

// Scratch: per-block partial column sums [NBLK1][D_COLS] floats = 1 MB
__device__ float4 g_partial[NBLK1 * D4];
__device__ float  g_blocksum[4];

// ---------------------------------------------------------------------------
// Kernel 1: streaming column-sum of (source - target).
// Each thread owns one float4 column group, sums 32 rows.
// ---------------------------------------------------------------------------
__global__ __launch_bounds__(256, 4)
void mmd_colsum_kernel(const float4* __restrict__ src,
                       const float4* __restrict__ tgt) {
    const int col  = threadIdx.x;           // 0..255
    const int blk  = blockIdx.x;            // 0..255
    const long base = (long)blk * ROWS_PER_BLK * D4 + col;

    float ax = 0.f, ay = 0.f, az = 0.f, aw = 0.f;

#pragma unroll 8
    for (int r = 0; r < ROWS_PER_BLK; r++) {
        float4 s = __ldg(&src[base + (long)r * D4]);
        float4 t = __ldg(&tgt[base + (long)r * D4]);
        ax += s.x - t.x;
        ay += s.y - t.y;
        az += s.z - t.z;
        aw += s.w - t.w;
    }

    float4 acc; acc.x = ax; acc.y = ay; acc.z = az; acc.w = aw;
    g_partial[blk * D4 + col] = acc;
}

// ---------------------------------------------------------------------------
// Kernel 2: finish column sums across the 256 block-partials, square,
// block-reduce. 4 blocks x 256 threads; thread d handles column d.
// ---------------------------------------------------------------------------
__global__ __launch_bounds__(256)
void mmd_reduce_kernel() {
    const int d = blockIdx.x * 256 + threadIdx.x;   // 0..1023
    const float* p = reinterpret_cast<const float*>(g_partial);

    float s = 0.f;
#pragma unroll 8
    for (int r = 0; r < NBLK1; r++) {
        s += p[(long)r * D_COLS + d];
    }
    float sq = s * s;

    // block reduction (shared memory, fixed order)
    __shared__ float red[256];
    red[threadIdx.x] = sq;
    __syncthreads();
#pragma unroll
    for (int off = 128; off > 0; off >>= 1) {
        if (threadIdx.x < off) red[threadIdx.x] += red[threadIdx.x + off];
        __syncthreads();
    }
    if (threadIdx.x == 0) g_blocksum[blockIdx.x] = red[0];
}

// ---------------------------------------------------------------------------
// Kernel 3: finalize scalar.
// ---------------------------------------------------------------------------
__global__ void mmd_final_kernel(float* __restrict__ out) {
    float s = g_blocksum[0] + g_blocksum[1] + g_blocksum[2] + g_blocksum[3];
    out[0] = s * (1.0f / ((float)N_ROWS * (float)N_ROWS));
}

// ---------------------------------------------------------------------------
extern "C" void kernel_launch(void* const* d_in, const int* in_sizes, int n_in,
                              void* d_out, int out_size) {
    const float4* src = (const float4*)d_in[0];
    const float4* tgt = (const float4*)d_in[1];
    float* out = (float*)d_out;

    mmd_colsum_kernel<<<NBLK1, 256>>>(src, tgt);
    mmd_reduce_kernel<<<4, 256>>>();
    mmd_final_kernel<<<1, 1>>>(out);
}

// round 2
// speedup vs baseline: 1.5271x; 1.5271x over previous
#include <cuda_runtime.h>
#include <cstdint>

// Problem constants
#define N_ROWS 8192
#define D_COLS 1024
#define D4     (D_COLS / 4)            // 256 float4 columns
#define NBLK1  1024                    // kernel1 blocks
#define ROWS_PER_BLK (N_ROWS / NBLK1)  // 8 rows per block

// Scratch (device globals; no allocation):
// stage-1 partial column sums: [NBLK1][D_COLS] floats = 4 MB (L2-resident)
__device__ float4 g_partial[NBLK1 * D4];
// stage-2 partial column sums: [32][D_COLS] floats = 128 KB
__device__ float  g_partial2[32 * D_COLS];

// ---------------------------------------------------------------------------
// Kernel 1: streaming column-sum of (source - target).
// 1024 blocks x 256 threads; thread owns one float4 column group, 8 rows.
// ---------------------------------------------------------------------------
__global__ __launch_bounds__(256)
void mmd_colsum_kernel(const float4* __restrict__ src,
                       const float4* __restrict__ tgt) {
    const int col  = threadIdx.x;            // 0..255
    const int blk  = blockIdx.x;             // 0..1023
    const long base = (long)blk * ROWS_PER_BLK * D4 + col;

    float ax = 0.f, ay = 0.f, az = 0.f, aw = 0.f;

#pragma unroll
    for (int r = 0; r < ROWS_PER_BLK; r++) {
        float4 s = __ldg(&src[base + (long)r * D4]);
        float4 t = __ldg(&tgt[base + (long)r * D4]);
        ax += s.x - t.x;
        ay += s.y - t.y;
        az += s.z - t.z;
        aw += s.w - t.w;
    }

    float4 acc; acc.x = ax; acc.y = ay; acc.z = az; acc.w = aw;
    g_partial[blk * D4 + col] = acc;
}

// ---------------------------------------------------------------------------
// Kernel 2: reduce 1024 partial rows -> 32 partial rows.
// 32 blocks x 1024 threads; block b sums partial rows [b*32, b*32+32) for
// its column (threadIdx.x). 4 MB read (L2), 128 KB written.
// ---------------------------------------------------------------------------
__global__ __launch_bounds__(1024)
void mmd_reduce_kernel() {
    const int d = threadIdx.x;               // column 0..1023
    const int b = blockIdx.x;                // 0..31
    const float* p = reinterpret_cast<const float*>(g_partial);

    float s = 0.f;
#pragma unroll
    for (int r = 0; r < 32; r++) {
        s += p[(long)(b * 32 + r) * D_COLS + d];
    }
    g_partial2[b * D_COLS + d] = s;
}

// ---------------------------------------------------------------------------
// Kernel 3: finish column sums (32 rows x 1024 cols, 128 KB L2-resident),
// square, block-reduce 1024 lanes, scale, write scalar. Fixed order ->
// deterministic.
// ---------------------------------------------------------------------------
__global__ __launch_bounds__(1024)
void mmd_final_kernel(float* __restrict__ out) {
    const int d = threadIdx.x;               // column 0..1023

    float s = 0.f;
#pragma unroll
    for (int r = 0; r < 32; r++) {
        s += g_partial2[r * D_COLS + d];
    }
    float sq = s * s;

    __shared__ float red[1024];
    red[d] = sq;
    __syncthreads();
#pragma unroll
    for (int off = 512; off > 0; off >>= 1) {
        if (d < off) red[d] += red[d + off];
        __syncthreads();
    }
    if (d == 0)
        out[0] = red[0] * (1.0f / ((float)N_ROWS * (float)N_ROWS));
}

// ---------------------------------------------------------------------------
extern "C" void kernel_launch(void* const* d_in, const int* in_sizes, int n_in,
                              void* d_out, int out_size) {
    const float4* src = (const float4*)d_in[0];
    const float4* tgt = (const float4*)d_in[1];
    float* out = (float*)d_out;

    mmd_colsum_kernel<<<NBLK1, 256>>>(src, tgt);
    mmd_reduce_kernel<<<32, 1024>>>();
    mmd_final_kernel<<<1, 1024>>>(out);
}

// round 3
// speedup vs baseline: 1.5610x; 1.0222x over previous
#include <cuda_runtime.h>
#include <cstdint>

// Problem constants
#define N_ROWS 8192
#define D_COLS 1024
#define D4     (D_COLS / 4)            // 256 float4 columns
#define NBLK1  1024                    // kernel1 blocks
#define ROWS_PER_BLK (N_ROWS / NBLK1)  // 8 rows per block

// Scratch (device globals; no allocation):
__device__ float4 g_partial[NBLK1 * D4];    // [1024][1024] floats = 4 MB
__device__ float  g_partial2[32 * D_COLS];  // 128 KB

// ---------------------------------------------------------------------------
// Kernel 1: streaming column-sum of (source - target).
// 1024 blocks x 256 threads. Each thread owns one float4 column group and
// 8 rows, processed as two batches of 4 rows with 8 front-batched LDG.128
// per batch (explicit MLP).
// ---------------------------------------------------------------------------
__global__ __launch_bounds__(256, 4)
void mmd_colsum_kernel(const float4* __restrict__ src,
                       const float4* __restrict__ tgt) {
    const int col  = threadIdx.x;            // 0..255
    const int blk  = blockIdx.x;             // 0..1023
    const long base = (long)blk * ROWS_PER_BLK * D4 + col;

    float ax = 0.f, ay = 0.f, az = 0.f, aw = 0.f;

#pragma unroll
    for (int half = 0; half < 2; half++) {
        const long b = base + (long)half * 4 * D4;
        // 8 independent loads, front-batched
        float4 s0 = __ldg(&src[b + 0 * D4]);
        float4 s1 = __ldg(&src[b + 1 * D4]);
        float4 s2 = __ldg(&src[b + 2 * D4]);
        float4 s3 = __ldg(&src[b + 3 * D4]);
        float4 t0 = __ldg(&tgt[b + 0 * D4]);
        float4 t1 = __ldg(&tgt[b + 1 * D4]);
        float4 t2 = __ldg(&tgt[b + 2 * D4]);
        float4 t3 = __ldg(&tgt[b + 3 * D4]);

        ax += (s0.x - t0.x) + (s1.x - t1.x) + (s2.x - t2.x) + (s3.x - t3.x);
        ay += (s0.y - t0.y) + (s1.y - t1.y) + (s2.y - t2.y) + (s3.y - t3.y);
        az += (s0.z - t0.z) + (s1.z - t1.z) + (s2.z - t2.z) + (s3.z - t3.z);
        aw += (s0.w - t0.w) + (s1.w - t1.w) + (s2.w - t2.w) + (s3.w - t3.w);
    }

    float4 acc; acc.x = ax; acc.y = ay; acc.z = az; acc.w = aw;
    g_partial[blk * D4 + col] = acc;
}

// ---------------------------------------------------------------------------
// Kernel 2: reduce 1024 partial rows -> 32 partial rows.
// 32 blocks x 1024 threads; block b sums partial rows [b*32, b*32+32).
// ---------------------------------------------------------------------------
__global__ __launch_bounds__(1024)
void mmd_reduce_kernel() {
    const int d = threadIdx.x;               // column 0..1023
    const int b = blockIdx.x;                // 0..31
    const float* p = reinterpret_cast<const float*>(g_partial);

    float s = 0.f;
#pragma unroll
    for (int r = 0; r < 32; r++) {
        s += p[(long)(b * 32 + r) * D_COLS + d];
    }
    g_partial2[b * D_COLS + d] = s;
}

// ---------------------------------------------------------------------------
// Kernel 3: finish column sums, square, block-reduce, scale, write scalar.
// ---------------------------------------------------------------------------
__global__ __launch_bounds__(1024)
void mmd_final_kernel(float* __restrict__ out) {
    const int d = threadIdx.x;               // column 0..1023

    float s = 0.f;
#pragma unroll
    for (int r = 0; r < 32; r++) {
        s += g_partial2[r * D_COLS + d];
    }
    float sq = s * s;

    __shared__ float red[1024];
    red[d] = sq;
    __syncthreads();
#pragma unroll
    for (int off = 512; off > 0; off >>= 1) {
        if (d < off) red[d] += red[d + off];
        __syncthreads();
    }
    if (d == 0)
        out[0] = red[0] * (1.0f / ((float)N_ROWS * (float)N_ROWS));
}

// ---------------------------------------------------------------------------
extern "C" void kernel_launch(void* const* d_in, const int* in_sizes, int n_in,
                              void* d_out, int out_size) {
    const float4* src = (const float4*)d_in[0];
    const float4* tgt = (const float4*)d_in[1];
    float* out = (float*)d_out;

    mmd_colsum_kernel<<<NBLK1, 256>>>(src, tgt);
    mmd_reduce_kernel<<<32, 1024>>>();
    mmd_final_kernel<<<1, 1024>>>(out);
}